// round 3
// baseline (speedup 1.0000x reference)
#include <cuda_runtime.h>
#include <math.h>

#define E_    50000
#define EPAD2 50176
#define N_    1000000
#define B_    8
#define L_    3
#define T_    3
#define NREL_ 401
#define R_    200
#define H_    256
#define G_    1024
#define TOPK_ 1000
#define BL_   24
#define NB_   296
#define TPB_  512

// ---------------- device scratch ----------------
__device__ int      g_cnt[2 * E_];          // concat: [0,E) head counts, [E,2E) tail counts
__device__ int      g_blksum[196];
__device__ int      g_off_h[E_ + 1];
__device__ int      g_off_t[E_ + 1];
__device__ int      g_cur_h[E_];
__device__ int      g_cur_t[E_];
__device__ unsigned g_csr_h[N_];            // packed: tail | (rel<<16)
__device__ unsigned g_csr_t[N_];            // packed: head | (rel<<16)
__device__ float    g_s[2][BL_ * E_];
__device__ float    g_norm[2][BL_];
__device__ float    g_preq[6 * B_ * G_];
__device__ float    g_pree[6 * B_ * G_];
__device__ float    g_hst[6 * B_ * H_];
__device__ float    g_cst[6 * B_ * H_];
__device__ float    g_hseq[6 * 4 * B_ * H_];
__device__ float    g_gates[6 * B_ * G_];
__device__ float    g_logits[T_ * BL_ * NREL_];
__device__ float    g_w[T_ * BL_ * NREL_];
__device__ float    g_th[BL_];
__device__ int      g_frcA, g_frcB;
__device__ unsigned g_fr_id[BL_ * E_];      // packed: (bl<<16) | e
__device__ float    g_fr_val[BL_ * E_];

__device__ unsigned g_bar_cnt = 0;
__device__ volatile unsigned g_bar_gen = 0;

__device__ __forceinline__ float sigm(float x) { return 1.f / (1.f + expf(-x)); }

// software grid barrier: safe because grid=296 <= 2/SM co-resident and the
// megakernel is the only kernel running (single stream, single graph node)
__device__ __forceinline__ void gridbar() {
    __threadfence();
    __syncthreads();
    if (threadIdx.x == 0) {
        unsigned gen = g_bar_gen;
        if (atomicAdd(&g_bar_cnt, 1u) == gridDim.x - 1) {
            g_bar_cnt = 0;
            __threadfence();
            g_bar_gen = gen + 1;
        } else {
            while (g_bar_gen == gen) __nanosleep(64);
        }
    }
    __syncthreads();
}

// -------- helpers for hop phases --------
__device__ void tc_select(int pp, int bl, int* s_hist) {
    __shared__ unsigned shp, shm;
    __shared__ int shk;
    const float* s = g_s[pp] + (size_t)bl * E_;
    int tid = threadIdx.x, lane = tid & 31;
    if (tid == 0) { shp = 0u; shm = 0u; shk = TOPK_; }
    __syncthreads();
    for (int pass = 0; pass < 4; ++pass) {
        int shift = 24 - 8 * pass;
        if (tid < 256) s_hist[tid] = 0;
        __syncthreads();
        unsigned mask = shm, pref = shp;
        for (int i = tid; i < EPAD2; i += TPB_) {
            unsigned bits = 0u; bool ok = false;
            if (i < E_) { bits = __float_as_uint(s[i]); ok = ((bits & mask) == pref); }
            int bin = (bits >> shift) & 255;
            unsigned act = __ballot_sync(0xffffffffu, ok);
            if (ok) {
                unsigned mm = __match_any_sync(act, bin);
                if (lane == __ffs(mm) - 1) atomicAdd(&s_hist[bin], __popc(mm));
            }
        }
        __syncthreads();
        if (tid == 0) {
            int cum = 0, krem = shk, sel = 0, newk = krem;
            for (int bn = 255; bn >= 0; --bn) {
                int c = s_hist[bn];
                if (cum + c >= krem) { sel = bn; newk = krem - cum; break; }
                cum += c;
            }
            shp = pref | ((unsigned)sel << shift);
            shm = mask | (0xFFu << shift);
            shk = newk;
        }
        __syncthreads();
    }
    if (tid == 0) g_th[bl] = __uint_as_float(shp);
}

__device__ void compact_phase(int pp, int* frc, int gid, int gsz) {
    int lane = threadIdx.x & 31;
    const int TOT = BL_ * E_;
    int nIter = (TOT + gsz - 1) / gsz;
    for (int it = 0; it < nIter; ++it) {
        int i = gid + it * gsz;
        float v = 0.f; bool keep = false; int bl = 0;
        if (i < TOT) {
            v = g_s[pp][i];
            if (v > 0.f) { bl = i / E_; keep = (v >= g_th[bl]); }
        }
        unsigned m = __ballot_sync(0xffffffffu, keep);
        if (m) {
            int ldr = __ffs(m) - 1;
            int base;
            if (lane == ldr) base = atomicAdd(frc, __popc(m));
            base = __shfl_sync(0xffffffffu, base, ldr);
            if (keep) {
                int off = base + __popc(m & ((1u << lane) - 1u));
                g_fr_id[off]  = ((unsigned)bl << 16) | (unsigned)(i - bl * E_);
                g_fr_val[off] = v;
            }
        }
    }
}

__device__ void propagate_phase(int t, int np, int nn, int sn, const int* frc,
                                int gid, int gsz) {
    int warp = gid >> 5;
    int lane = threadIdx.x & 31;
    int nwarps = gsz >> 5;
    int cnt = *frc;
    for (int ent = warp; ent < cnt; ent += nwarps) {
        unsigned id = g_fr_id[ent];
        int bl = id >> 16;
        int e  = id & 0xFFFFu;
        float v = g_fr_val[ent] / fmaxf(g_norm[np][bl], 1e-7f);
        const float* wr = g_w + (t * BL_ + bl) * NREL_;
        float* outp = g_s[sn] + (size_t)bl * E_;
        float lsum = 0.f;
        if (lane == 0) {
            float m = wr[NREL_ - 1] * v;
            atomicAdd(&outp[e], m);
            lsum += m;
        }
        int a0 = g_off_h[e], a1 = g_off_h[e + 1];
        for (int i = a0 + lane; i < a1; i += 32) {
            unsigned pk = g_csr_h[i];
            float m = v * wr[pk >> 16];
            atomicAdd(&outp[pk & 0xFFFFu], m);
            lsum += m;
        }
        a0 = g_off_t[e]; a1 = g_off_t[e + 1];
        for (int i = a0 + lane; i < a1; i += 32) {
            unsigned pk = g_csr_t[i];
            float m = v * wr[(pk >> 16) + R_];
            atomicAdd(&outp[pk & 0xFFFFu], m);
            lsum += m;
        }
        for (int o = 16; o > 0; o >>= 1) lsum += __shfl_down_sync(0xffffffffu, lsum, o);
        if (lane == 0) atomicAdd(&g_norm[nn][bl], lsum);
    }
}

// ---------------- the megakernel ----------------
__global__ void __launch_bounds__(TPB_, 2)
mega_kernel(const int* __restrict__ input_x, const int* __restrict__ input_r,
            const int* __restrict__ e2, const int* __restrict__ t2e,
            const int* __restrict__ r2, const float* __restrict__ emb,
            const float* __restrict__ Wihf, const float* __restrict__ Whhf,
            const float* __restrict__ bihf, const float* __restrict__ bhhf,
            const float* __restrict__ Wihb, const float* __restrict__ Whhb,
            const float* __restrict__ bihb, const float* __restrict__ bhhb,
            const float* __restrict__ linW, const float* __restrict__ linb,
            float* __restrict__ out) {
    const int bid = blockIdx.x, tid = threadIdx.x;
    const int gid = bid * TPB_ + tid;
    const int gsz = gridDim.x * TPB_;
    __shared__ int   s_scan[TPB_];
    __shared__ int   s_hist[256];
    __shared__ float s_red[TPB_];
    __shared__ float s_buf[416];

    const int4* h4  = (const int4*)e2;
    const int4* t24 = (const int4*)(e2 + 2 * N_);
    const int4* t4  = (const int4*)(t2e + N_);
    const int4* r4  = (const int4*)r2;

    // ===== P0: zero everything =====
    for (int i = gid; i < 2 * E_; i += gsz) g_cnt[i] = 0;
    {
        float4 z4 = make_float4(0.f, 0.f, 0.f, 0.f);
        float4* sv = (float4*)(&g_s[0][0]);
        for (int i = gid; i < 2 * BL_ * E_ / 4; i += gsz) sv[i] = z4;
    }
    if (gid < 2 * BL_) ((float*)g_norm)[gid] = 0.f;
    if (gid == 0) { g_frcA = 0; g_frcB = 0; }
    gridbar();

    // ===== P1: histogram =====
    for (int i = gid; i < N_ / 4; i += gsz) {
        int4 h = h4[i], t = t24[i];
        atomicAdd(&g_cnt[h.x], 1); atomicAdd(&g_cnt[h.y], 1);
        atomicAdd(&g_cnt[h.z], 1); atomicAdd(&g_cnt[h.w], 1);
        atomicAdd(&g_cnt[E_ + t.x], 1); atomicAdd(&g_cnt[E_ + t.y], 1);
        atomicAdd(&g_cnt[E_ + t.z], 1); atomicAdd(&g_cnt[E_ + t.w], 1);
    }
    gridbar();

    // ===== P2: per-block tile sums of concat counter array (196 tiles of 512) =====
    if (bid < 196) {
        int j = bid * TPB_ + tid;
        int v = (j < 2 * E_) ? g_cnt[j] : 0;
        s_scan[tid] = v;
        __syncthreads();
        for (int o = 256; o > 0; o >>= 1) {
            if (tid < o) s_scan[tid] += s_scan[tid + o];
            __syncthreads();
        }
        if (tid == 0) g_blksum[bid] = s_scan[0];
    }
    gridbar();

    // ===== P3: tile scan + offset write =====
    if (bid < 196) {
        // reduction helper over s_scan
        int base, sumAll, th_part;
        {
            int v = (tid < 196 && tid < bid) ? g_blksum[tid] : 0;
            s_scan[tid] = v; __syncthreads();
            for (int o = 256; o > 0; o >>= 1) { if (tid < o) s_scan[tid] += s_scan[tid + o]; __syncthreads(); }
            base = s_scan[0]; __syncthreads();
            v = (tid < 196) ? g_blksum[tid] : 0;
            s_scan[tid] = v; __syncthreads();
            for (int o = 256; o > 0; o >>= 1) { if (tid < o) s_scan[tid] += s_scan[tid + o]; __syncthreads(); }
            sumAll = s_scan[0]; __syncthreads();
            // total_h = sum blksum[0..96] + sum C[49664..50000)
            v = (tid < 97) ? g_blksum[tid] : 0;
            if (tid >= 128 && tid < 128 + 336) v = g_cnt[49664 + (tid - 128)];
            s_scan[tid] = v; __syncthreads();
            for (int o = 256; o > 0; o >>= 1) { if (tid < o) s_scan[tid] += s_scan[tid + o]; __syncthreads(); }
            th_part = s_scan[0]; __syncthreads();
        }
        int total_h = th_part;
        int j = bid * TPB_ + tid;
        int v = (j < 2 * E_) ? g_cnt[j] : 0;
        s_scan[tid] = v;
        __syncthreads();
        // inclusive Hillis-Steele over 512
        for (int d = 1; d < TPB_; d <<= 1) {
            int t = (tid >= d) ? s_scan[tid - d] : 0;
            __syncthreads();
            s_scan[tid] += t;
            __syncthreads();
        }
        int p = base + s_scan[tid] - v;
        if (j < 2 * E_) {
            if (j < E_) { g_off_h[j] = p; g_cur_h[j] = p; }
            else        { g_off_t[j - E_] = p - total_h; g_cur_t[j - E_] = p - total_h; }
        }
        if (j == E_) g_off_h[E_] = total_h;
        if (bid == 0 && tid == 0) g_off_t[E_] = sumAll - total_h;
    }
    gridbar();

    // ===== P4: scatter CSR =====
    for (int i = gid; i < N_ / 4; i += gsz) {
        int4 h = h4[i], t = t4[i], r = r4[i], t2 = t24[i];
#define DO1(hx, tx, rx, t2x) { \
        int p = atomicAdd(&g_cur_h[hx], 1); \
        g_csr_h[p] = (unsigned)(tx) | ((unsigned)(rx) << 16); \
        int q = atomicAdd(&g_cur_t[t2x], 1); \
        g_csr_t[q] = (unsigned)(hx) | ((unsigned)(rx) << 16); }
        DO1(h.x, t.x, r.x, t2.x); DO1(h.y, t.y, r.y, t2.y);
        DO1(h.z, t.z, r.z, t2.z); DO1(h.w, t.w, r.w, t2.w);
#undef DO1
    }
    gridbar();

    // ===== P5: LSTM input projections (pre) =====
    if (bid < 96) {
        int g = gid;                 // < 49152
        int p = g & 7, row = g >> 3;
        int ld = row >> 10, j = row & 1023;
        int dir = ld / 3, l = ld - dir * 3;
        const float4* w4 = (const float4*)((dir ? Wihb : Wihf) + ((size_t)(l * G_ + j)) * H_) + p * 8;
        const float4* e4 = (const float4*)(emb + (size_t)(NREL_ - 1) * H_) + p * 8;
        const float4* q4[B_];
        float aq[B_];
#pragma unroll
        for (int b = 0; b < B_; ++b) {
            q4[b] = (const float4*)(emb + (size_t)input_r[b] * H_) + p * 8;
            aq[b] = 0.f;
        }
        float ae = 0.f;
#pragma unroll
        for (int k = 0; k < 8; ++k) {
            float4 w = w4[k], e = e4[k];
            ae += w.x * e.x + w.y * e.y + w.z * e.z + w.w * e.w;
#pragma unroll
            for (int b = 0; b < B_; ++b) {
                float4 q = q4[b][k];
                aq[b] += w.x * q.x + w.y * q.y + w.z * q.z + w.w * q.w;
            }
        }
#pragma unroll
        for (int o = 1; o <= 4; o <<= 1) {
            ae += __shfl_xor_sync(0xffffffffu, ae, o);
#pragma unroll
            for (int b = 0; b < B_; ++b) aq[b] += __shfl_xor_sync(0xffffffffu, aq[b], o);
        }
        if (p == 0) {
            float bias = (dir ? bihb : bihf)[l * G_ + j] + (dir ? bhhb : bhhf)[l * G_ + j];
#pragma unroll
            for (int b = 0; b < B_; ++b) {
                int idx = (ld * 8 + b) * G_ + j;
                g_preq[idx] = aq[b] + bias;
                g_pree[idx] = ae + bias;
            }
        }
    }
    gridbar();

    // ===== LSTM steps 0..3 =====
    for (int s = 0; s < 4; ++s) {
        if (s > 0) {
            // gates = Whh @ h
            if (bid < 96) {
                int g = gid;
                int p = g & 7, row = g >> 3;
                int ld = row >> 10, j = row & 1023;
                int dir = ld / 3, l = ld - dir * 3;
                const float4* w4 = (const float4*)((dir ? Whhb : Whhf) + ((size_t)(l * G_ + j)) * H_) + p * 8;
                const float4* hb = (const float4*)g_hst + (ld * 8) * 64 + p * 8;
                float acc[B_];
#pragma unroll
                for (int b = 0; b < B_; ++b) acc[b] = 0.f;
#pragma unroll
                for (int k = 0; k < 8; ++k) {
                    float4 w = w4[k];
#pragma unroll
                    for (int b = 0; b < B_; ++b) {
                        float4 h = hb[b * 64 + k];
                        acc[b] += w.x * h.x + w.y * h.y + w.z * h.z + w.w * h.w;
                    }
                }
#pragma unroll
                for (int o = 1; o <= 4; o <<= 1)
#pragma unroll
                    for (int b = 0; b < B_; ++b) acc[b] += __shfl_xor_sync(0xffffffffu, acc[b], o);
                if (p == 0) {
                    const float* pre = ((dir == 0) && (s == 3)) ? g_pree : g_preq;
#pragma unroll
                    for (int b = 0; b < B_; ++b) {
                        int idx = (ld * 8 + b) * G_ + j;
                        g_gates[idx] = pre[idx] + acc[b];
                    }
                }
            }
            gridbar();
        }
        // cell/hidden update
        if (gid < 6 * B_ * H_) {
            int idx = gid;
            int ld = idx >> 11;
            int b  = (idx >> 8) & 7;
            int u  = idx & 255;
            int base2 = (ld * 8 + b) * G_;
            float gi, gf, gg, go, cprev;
            if (s == 0) {
                const float* src = (ld >= 3) ? g_pree : g_preq;
                gi = src[base2 + u]; gf = src[base2 + 256 + u];
                gg = src[base2 + 512 + u]; go = src[base2 + 768 + u];
                cprev = 0.f;
            } else {
                gi = g_gates[base2 + u]; gf = g_gates[base2 + 256 + u];
                gg = g_gates[base2 + 512 + u]; go = g_gates[base2 + 768 + u];
                cprev = g_cst[idx];
            }
            float c = sigm(gf) * cprev + sigm(gi) * tanhf(gg);
            float h = sigm(go) * tanhf(c);
            g_cst[idx] = c;
            g_hst[idx] = h;
            g_hseq[((ld * 4 + s) * 8 + b) * H_ + u] = h;
        }
        gridbar();
    }

    // ===== logits =====
    {
        const int TOTAL = NREL_ * 9 * 8;   // 28872
        if (bid < 57) {
            int g = (gid < TOTAL) ? gid : (TOTAL - 1);
            int n = g / 72;
            int rem = g % 72;
            int tl = rem >> 3;
            int p = g & 7;
            int t = tl / 3, l = tl - t * 3;
            const float4* w1 = (const float4*)(linW + (size_t)n * 2 * H_) + p * 8;
            const float4* w2 = w1 + 64;
            const float4* hf = (const float4*)g_hseq + ((l * 4 + t) * 8) * 64 + p * 8;
            const float4* hb = (const float4*)g_hseq + (((3 + l) * 4 + (3 - t)) * 8) * 64 + p * 8;
            float acc[B_];
#pragma unroll
            for (int b = 0; b < B_; ++b) acc[b] = 0.f;
#pragma unroll
            for (int k = 0; k < 8; ++k) {
                float4 wa = w1[k], wb = w2[k];
#pragma unroll
                for (int b = 0; b < B_; ++b) {
                    float4 a = hf[b * 64 + k];
                    float4 c = hb[b * 64 + k];
                    acc[b] += a.x * wa.x + a.y * wa.y + a.z * wa.z + a.w * wa.w
                            + c.x * wb.x + c.y * wb.y + c.z * wb.z + c.w * wb.w;
                }
            }
#pragma unroll
            for (int o = 1; o <= 4; o <<= 1)
#pragma unroll
                for (int b = 0; b < B_; ++b) acc[b] += __shfl_xor_sync(0xffffffffu, acc[b], o);
            if (gid < TOTAL && p == 0) {
                float bb = linb[n];
#pragma unroll
                for (int b = 0; b < B_; ++b)
                    g_logits[(t * BL_ + b * 3 + l) * NREL_ + n] = acc[b] + bb;
            }
        }
    }
    gridbar();

    // ===== softmax (72 rows) =====
    if (bid < T_ * BL_) {
        const float* lg = g_logits + bid * NREL_;
        float* wout = g_w + bid * NREL_;
        float lmax = -1e30f;
        for (int i = tid; i < NREL_; i += TPB_) {
            float v = lg[i] * 0.1f;
            s_buf[i] = v;
            lmax = fmaxf(lmax, v);
        }
        s_red[tid] = lmax; __syncthreads();
        for (int o = 256; o > 0; o >>= 1) { if (tid < o) s_red[tid] = fmaxf(s_red[tid], s_red[tid + o]); __syncthreads(); }
        float m = s_red[0];
        __syncthreads();
        float lsum = 0.f;
        for (int i = tid; i < NREL_; i += TPB_) {
            float ex = expf(s_buf[i] - m);
            s_buf[i] = ex;
            lsum += ex;
        }
        s_red[tid] = lsum; __syncthreads();
        for (int o = 256; o > 0; o >>= 1) { if (tid < o) s_red[tid] += s_red[tid + o]; __syncthreads(); }
        float inv = 1.f / s_red[0];
        for (int i = tid; i < NREL_; i += TPB_) wout[i] = s_buf[i] * inv;
    }
    gridbar();

    // ===== hop 0 (one-hot frontier), 24 blocks =====
    if (bid < BL_) {
        int bl = bid;
        int b = bl / 3;
        int e = input_x[b];
        const float* wr = g_w + bl * NREL_;
        float* outp = g_s[1] + (size_t)bl * E_;
        float lsum = 0.f;
        if (tid == 0) { float m = wr[NREL_ - 1]; atomicAdd(&outp[e], m); lsum = m; }
        int a0 = g_off_h[e], a1 = g_off_h[e + 1];
        for (int i = a0 + tid; i < a1; i += TPB_) {
            unsigned pk = g_csr_h[i];
            float m = wr[pk >> 16];
            atomicAdd(&outp[pk & 0xFFFFu], m);
            lsum += m;
        }
        a0 = g_off_t[e]; a1 = g_off_t[e + 1];
        for (int i = a0 + tid; i < a1; i += TPB_) {
            unsigned pk = g_csr_t[i];
            float m = wr[(pk >> 16) + R_];
            atomicAdd(&outp[pk & 0xFFFFu], m);
            lsum += m;
        }
        s_red[tid] = lsum; __syncthreads();
        for (int o = 256; o > 0; o >>= 1) { if (tid < o) s_red[tid] += s_red[tid + o]; __syncthreads(); }
        if (tid == 0) g_norm[1][bl] = s_red[0];
    }
    gridbar();

    // ===== hop 1: select -> compact -> propagate =====
    if (bid < BL_) tc_select(1, bid, s_hist);
    gridbar();
    compact_phase(1, &g_frcA, gid, gsz);
    gridbar();
    propagate_phase(1, 1, 0, 0, &g_frcA, gid, gsz);
    gridbar();

    // ===== hop 2: select (idle blocks re-zero s[1], norm[1], frcB) =====
    if (bid < BL_) {
        tc_select(0, bid, s_hist);
    } else {
        int zgid = (bid - BL_) * TPB_ + tid;
        int zstride = (gridDim.x - BL_) * TPB_;
        float4 z4 = make_float4(0.f, 0.f, 0.f, 0.f);
        float4* s1v = (float4*)(&g_s[1][0]);
        for (int i = zgid; i < BL_ * E_ / 4; i += zstride) s1v[i] = z4;
        if (zgid < BL_) g_norm[1][zgid] = 0.f;
        if (zgid == 0) g_frcB = 0;
    }
    gridbar();
    compact_phase(0, &g_frcB, gid, gsz);
    gridbar();
    propagate_phase(2, 0, 1, 1, &g_frcB, gid, gsz);
    gridbar();

    // ===== output =====
    for (int idx = gid; idx < B_ * E_; idx += gsz) {
        int b = idx / E_;
        int e = idx - b * E_;
        float acc = 0.f;
#pragma unroll
        for (int l = 0; l < L_; ++l) {
            int bl = b * 3 + l;
            acc += g_s[1][(size_t)bl * E_ + e] / fmaxf(g_norm[1][bl], 1e-7f);
        }
        out[idx] = acc;
    }
}

// ---------------- launch ----------------
extern "C" void kernel_launch(void* const* d_in, const int* in_sizes, int n_in,
                              void* d_out, int out_size) {
    (void)in_sizes; (void)n_in; (void)out_size;
    mega_kernel<<<NB_, TPB_>>>(
        (const int*)d_in[0], (const int*)d_in[1], (const int*)d_in[2],
        (const int*)d_in[3], (const int*)d_in[4], (const float*)d_in[5],
        (const float*)d_in[6], (const float*)d_in[7], (const float*)d_in[8],
        (const float*)d_in[9], (const float*)d_in[10], (const float*)d_in[11],
        (const float*)d_in[12], (const float*)d_in[13], (const float*)d_in[14],
        (const float*)d_in[15], (float*)d_out);
}

// round 6
// speedup vs baseline: 1.2352x; 1.2352x over previous
#include <cuda_runtime.h>
#include <math.h>
#include <cstddef>

#define E_    50000
#define N_    1000000
#define B_    8
#define L_    3
#define T_    3
#define NREL_ 401
#define R_    200
#define H_    256
#define G_    1024
#define TOPK_ 1000
#define BL_   24
#define CAP_  64

// ---------------- zeroed-every-launch block (single memset) ----------------
struct Zs {
    int   cnt_h[E_];
    int   cnt_t[E_];
    int   cnnz[BL_];
    int   frA, frB;
    int   spill;
    float nrm[3][BL_];
};
__device__ Zs gZ;

// ---------------- persistent scratch ----------------
__device__ unsigned g_ell_h[(size_t)E_ * CAP_];   // tail | (rel<<16)
__device__ unsigned g_ell_t[(size_t)E_ * CAP_];   // head | (rel<<16)
__device__ int      g_sp_ent[2 * N_];
__device__ unsigned g_sp_pay[2 * N_];             // tgt | (rel<<16) | (dir<<31)
__device__ float    g_s[2][BL_ * E_];             // invariant: all-zero at launch entry
__device__ int      g_cand[(size_t)BL_ * E_];
__device__ unsigned g_fr_id[BL_ * E_];            // (bl<<16) | e
__device__ float    g_fr_val[BL_ * E_];
// lstm
__device__ float    g_preq[6 * B_ * G_], g_pree[6 * B_ * G_], g_gates[6 * B_ * G_];
__device__ float    g_hst[6 * B_ * H_], g_cst[6 * B_ * H_];
__device__ float    g_hseq[24 * B_ * H_];
__device__ float    g_logits[T_ * BL_ * NREL_], g_w[T_ * BL_ * NREL_];

__device__ unsigned g_bar_cnt = 0;
__device__ volatile unsigned g_bar_gen = 0;

__device__ __forceinline__ float sigm(float x) { return 1.f / (1.f + expf(-x)); }

// grid barrier (used only by lstm_kernel: 96 blocks <= 148 SMs -> co-resident;
// concurrent kernels on the other stream never wait on this one, so no deadlock)
__device__ __forceinline__ void gridbar() {
    __threadfence();
    __syncthreads();
    if (threadIdx.x == 0) {
        unsigned gen = g_bar_gen;
        if (atomicAdd(&g_bar_cnt, 1u) == gridDim.x - 1) {
            g_bar_cnt = 0;
            __threadfence();
            g_bar_gen = gen + 1;
        } else {
            while (g_bar_gen == gen) __nanosleep(128);
        }
    }
    __syncthreads();
}

// ---------------- single-pass ELL build (spill-exact) ----------------
__global__ void build_kernel(const int4* __restrict__ h4, const int4* __restrict__ t4,
                             const int4* __restrict__ r4, const int4* __restrict__ t24) {
    int i = blockIdx.x * 512 + threadIdx.x;
    if (i >= N_ / 4) return;
    int4 h = h4[i], t = t4[i], r = r4[i], t2 = t24[i];
#define DO1(hx, tx, rx, t2x) { \
    int pos = atomicAdd(&gZ.cnt_h[hx], 1); \
    unsigned pay = (unsigned)(tx) | ((unsigned)(rx) << 16); \
    if (pos < CAP_) g_ell_h[(size_t)(hx) * CAP_ + pos] = pay; \
    else { int sp = atomicAdd(&gZ.spill, 1); g_sp_ent[sp] = (hx); g_sp_pay[sp] = pay; } \
    int pos2 = atomicAdd(&gZ.cnt_t[t2x], 1); \
    unsigned pay2 = (unsigned)(hx) | ((unsigned)(rx) << 16); \
    if (pos2 < CAP_) g_ell_t[(size_t)(t2x) * CAP_ + pos2] = pay2; \
    else { int sp = atomicAdd(&gZ.spill, 1); g_sp_ent[sp] = (t2x); g_sp_pay[sp] = pay2 | 0x80000000u; } }
    DO1(h.x, t.x, r.x, t2.x); DO1(h.y, t.y, r.y, t2.y);
    DO1(h.z, t.z, r.z, t2.z); DO1(h.w, t.w, r.w, t2.w);
#undef DO1
}

// ---------------- fused BiLSTM + logits + softmax (96 blocks) ----------------
__global__ void __launch_bounds__(512)
lstm_kernel(const int* __restrict__ input_r, const float* __restrict__ emb,
            const float* __restrict__ Wihf, const float* __restrict__ Whhf,
            const float* __restrict__ bihf, const float* __restrict__ bhhf,
            const float* __restrict__ Wihb, const float* __restrict__ Whhb,
            const float* __restrict__ bihb, const float* __restrict__ bhhb,
            const float* __restrict__ linW, const float* __restrict__ linb) {
    const int bid = blockIdx.x, tid = threadIdx.x;
    const int gid = bid * 512 + tid;
    __shared__ float s_buf[416];
    __shared__ float s_red[512];

    // --- pre: input projections for q and emb[-1] ---
    {
        int p = gid & 7, row = gid >> 3;          // 49152 threads exactly
        int ld = row >> 10, j = row & 1023;
        int dir = ld / 3, l = ld - dir * 3;
        const float4* w4 = (const float4*)((dir ? Wihb : Wihf) + ((size_t)(l * G_ + j)) * H_) + p * 8;
        const float4* e4 = (const float4*)(emb + (size_t)(NREL_ - 1) * H_) + p * 8;
        const float4* q4[B_];
        float aq[B_];
#pragma unroll
        for (int b = 0; b < B_; ++b) {
            q4[b] = (const float4*)(emb + (size_t)input_r[b] * H_) + p * 8;
            aq[b] = 0.f;
        }
        float ae = 0.f;
#pragma unroll
        for (int k = 0; k < 8; ++k) {
            float4 w = w4[k], e = e4[k];
            ae += w.x * e.x + w.y * e.y + w.z * e.z + w.w * e.w;
#pragma unroll
            for (int b = 0; b < B_; ++b) {
                float4 q = q4[b][k];
                aq[b] += w.x * q.x + w.y * q.y + w.z * q.z + w.w * q.w;
            }
        }
#pragma unroll
        for (int o = 1; o <= 4; o <<= 1) {
            ae += __shfl_xor_sync(0xffffffffu, ae, o);
#pragma unroll
            for (int b = 0; b < B_; ++b) aq[b] += __shfl_xor_sync(0xffffffffu, aq[b], o);
        }
        if (p == 0) {
            float bias = (dir ? bihb : bihf)[l * G_ + j] + (dir ? bhhb : bhhf)[l * G_ + j];
#pragma unroll
            for (int b = 0; b < B_; ++b) {
                int idx = (ld * 8 + b) * G_ + j;
                g_preq[idx] = aq[b] + bias;
                g_pree[idx] = ae + bias;
            }
        }
    }
    gridbar();

    // --- 4 recurrence steps ---
    for (int s = 0; s < 4; ++s) {
        if (s > 0) {
            int p = gid & 7, row = gid >> 3;
            int ld = row >> 10, j = row & 1023;
            int dir = ld / 3, l = ld - dir * 3;
            const float4* w4 = (const float4*)((dir ? Whhb : Whhf) + ((size_t)(l * G_ + j)) * H_) + p * 8;
            const float4* hb = (const float4*)g_hst + (ld * 8) * 64 + p * 8;
            float acc[B_];
#pragma unroll
            for (int b = 0; b < B_; ++b) acc[b] = 0.f;
#pragma unroll
            for (int k = 0; k < 8; ++k) {
                float4 w = w4[k];
#pragma unroll
                for (int b = 0; b < B_; ++b) {
                    float4 h = hb[b * 64 + k];
                    acc[b] += w.x * h.x + w.y * h.y + w.z * h.z + w.w * h.w;
                }
            }
#pragma unroll
            for (int o = 1; o <= 4; o <<= 1)
#pragma unroll
                for (int b = 0; b < B_; ++b) acc[b] += __shfl_xor_sync(0xffffffffu, acc[b], o);
            if (p == 0) {
                const float* pre = ((dir == 0) && (s == 3)) ? g_pree : g_preq;
#pragma unroll
                for (int b = 0; b < B_; ++b) {
                    int idx = (ld * 8 + b) * G_ + j;
                    g_gates[idx] = pre[idx] + acc[b];
                }
            }
            gridbar();
        }
        if (gid < 6 * B_ * H_) {
            int idx = gid;
            int ld = idx >> 11;
            int b  = (idx >> 8) & 7;
            int u  = idx & 255;
            int base2 = (ld * 8 + b) * G_;
            float gi, gf, gg, go, cprev;
            if (s == 0) {
                const float* src = (ld >= 3) ? g_pree : g_preq;
                gi = src[base2 + u]; gf = src[base2 + 256 + u];
                gg = src[base2 + 512 + u]; go = src[base2 + 768 + u];
                cprev = 0.f;
            } else {
                gi = g_gates[base2 + u]; gf = g_gates[base2 + 256 + u];
                gg = g_gates[base2 + 512 + u]; go = g_gates[base2 + 768 + u];
                cprev = g_cst[idx];
            }
            float c = sigm(gf) * cprev + sigm(gi) * tanhf(gg);
            float h = sigm(go) * tanhf(c);
            g_cst[idx] = c;
            g_hst[idx] = h;
            g_hseq[((ld * 4 + s) * 8 + b) * H_ + u] = h;
        }
        gridbar();
    }

    // --- logits ---
    {
        const int TOTAL = NREL_ * 9 * 8;   // 28872
        int g = (gid < TOTAL) ? gid : (TOTAL - 1);
        int n = g / 72;
        int rem = g % 72;
        int tl = rem >> 3;
        int p = g & 7;
        int t = tl / 3, l = tl - t * 3;
        const float4* w1 = (const float4*)(linW + (size_t)n * 2 * H_) + p * 8;
        const float4* w2 = w1 + 64;
        const float4* hf = (const float4*)g_hseq + ((l * 4 + t) * 8) * 64 + p * 8;
        const float4* hb = (const float4*)g_hseq + (((3 + l) * 4 + (3 - t)) * 8) * 64 + p * 8;
        float acc[B_];
#pragma unroll
        for (int b = 0; b < B_; ++b) acc[b] = 0.f;
#pragma unroll
        for (int k = 0; k < 8; ++k) {
            float4 wa = w1[k], wb = w2[k];
#pragma unroll
            for (int b = 0; b < B_; ++b) {
                float4 a = hf[b * 64 + k];
                float4 c = hb[b * 64 + k];
                acc[b] += a.x * wa.x + a.y * wa.y + a.z * wa.z + a.w * wa.w
                        + c.x * wb.x + c.y * wb.y + c.z * wb.z + c.w * wb.w;
            }
        }
#pragma unroll
        for (int o = 1; o <= 4; o <<= 1)
#pragma unroll
            for (int b = 0; b < B_; ++b) acc[b] += __shfl_xor_sync(0xffffffffu, acc[b], o);
        if (gid < TOTAL && p == 0) {
            float bb = linb[n];
#pragma unroll
            for (int b = 0; b < B_; ++b)
                g_logits[(t * BL_ + b * 3 + l) * NREL_ + n] = acc[b] + bb;
        }
    }
    gridbar();

    // --- softmax (72 rows over first 72 blocks) ---
    if (bid < T_ * BL_) {
        const float* lg = g_logits + bid * NREL_;
        float* wout = g_w + bid * NREL_;
        float lmax = -1e30f;
        for (int i = tid; i < NREL_; i += 512) {
            float v = lg[i] * 0.1f;
            s_buf[i] = v;
            lmax = fmaxf(lmax, v);
        }
        s_red[tid] = lmax; __syncthreads();
        for (int o = 256; o > 0; o >>= 1) { if (tid < o) s_red[tid] = fmaxf(s_red[tid], s_red[tid + o]); __syncthreads(); }
        float m = s_red[0];
        __syncthreads();
        float lsum = 0.f;
        for (int i = tid; i < NREL_; i += 512) {
            float ex = expf(s_buf[i] - m);
            s_buf[i] = ex;
            lsum += ex;
        }
        s_red[tid] = lsum; __syncthreads();
        for (int o = 256; o > 0; o >>= 1) { if (tid < o) s_red[tid] += s_red[tid + o]; __syncthreads(); }
        float inv = 1.f / s_red[0];
        for (int i = tid; i < NREL_; i += 512) wout[i] = s_buf[i] * inv;
    }
}

// ---------------- message add with first-touch candidate tracking ----------------
__device__ __forceinline__ void addmsg(float* __restrict__ outp, int tgt, float m,
                                       int bl, int track, float& lsum) {
    float old = atomicAdd(&outp[tgt], m);
    if (track && old == 0.f && m > 0.f) {
        int p = atomicAdd(&gZ.cnnz[bl], 1);
        g_cand[(size_t)bl * E_ + p] = tgt;
    }
    lsum += m;
}

// ---------------- hop 0: one block per (b,l), one-hot frontier ----------------
__global__ void hop0_kernel(const int* __restrict__ input_x) {
    int bl = blockIdx.x, tid = threadIdx.x;
    int e = input_x[bl / 3];
    const float* wr = g_w + bl * NREL_;   // t = 0
    float* outp = g_s[1] + (size_t)bl * E_;
    float lsum = 0.f;
    if (tid == 0) addmsg(outp, e, wr[NREL_ - 1], bl, 1, lsum);
    int ch = min(gZ.cnt_h[e], CAP_);
    const unsigned* row = g_ell_h + (size_t)e * CAP_;
    for (int i = tid; i < ch; i += 512) {
        unsigned pk = row[i];
        addmsg(outp, pk & 0xFFFFu, wr[pk >> 16], bl, 1, lsum);
    }
    int ct = min(gZ.cnt_t[e], CAP_);
    row = g_ell_t + (size_t)e * CAP_;
    for (int i = tid; i < ct; i += 512) {
        unsigned pk = row[i];
        addmsg(outp, pk & 0xFFFFu, wr[(pk >> 16) + R_], bl, 1, lsum);
    }
    int sc = gZ.spill;
    for (int i = tid; i < sc; i += 512) {
        if (g_sp_ent[i] == e) {
            unsigned pk = g_sp_pay[i];
            int widx = ((pk >> 16) & 0x7FFF) + ((pk >> 31) ? R_ : 0);
            addmsg(outp, pk & 0xFFFFu, wr[widx], bl, 1, lsum);
        }
    }
    __shared__ float s_red[512];
    s_red[tid] = lsum; __syncthreads();
    for (int o = 256; o > 0; o >>= 1) { if (tid < o) s_red[tid] += s_red[tid + o]; __syncthreads(); }
    if (tid == 0) gZ.nrm[0][bl] = s_red[0];
}

// ---------------- tc: sparse select + compact + sparse zero ----------------
__global__ void tc_kernel(int pp, int* __restrict__ frc) {
    int bl = blockIdx.x, tid = threadIdx.x, lane = tid & 31;
    float* s = g_s[pp] + (size_t)bl * E_;
    const int* cand = g_cand + (size_t)bl * E_;
    int nnz = gZ.cnnz[bl];
    __shared__ int hist[256];
    __shared__ unsigned shp, shm;
    __shared__ int shk;
    float th = 0.f;
    if (nnz > TOPK_) {
        if (tid == 0) { shp = 0u; shm = 0u; shk = TOPK_; }
        __syncthreads();
        for (int pass = 0; pass < 4; ++pass) {
            int shift = 24 - 8 * pass;
            if (tid < 256) hist[tid] = 0;
            __syncthreads();
            unsigned mask = shm, pref = shp;
            for (int i0 = 0; i0 < nnz; i0 += 512) {
                int i = i0 + tid;
                unsigned bits = 0u; bool ok = false;
                if (i < nnz) { bits = __float_as_uint(s[cand[i]]); ok = ((bits & mask) == pref); }
                int bin = (bits >> shift) & 255;
                unsigned act = __ballot_sync(0xffffffffu, ok);
                if (ok) {
                    unsigned mm = __match_any_sync(act, bin);
                    if (lane == __ffs(mm) - 1) atomicAdd(&hist[bin], __popc(mm));
                }
            }
            __syncthreads();
            if (tid == 0) {
                int cum = 0, krem = shk, sel = 0, newk = krem;
                for (int bn = 255; bn >= 0; --bn) {
                    int c = hist[bn];
                    if (cum + c >= krem) { sel = bn; newk = krem - cum; break; }
                    cum += c;
                }
                shp = pref | ((unsigned)sel << shift);
                shm = mask | (0xFFu << shift);
                shk = newk;
            }
            __syncthreads();
        }
        th = __uint_as_float(shp);
    }
    __syncthreads();
    // compact (keep v >= th) + zero consumed entries
    for (int i0 = 0; i0 < nnz; i0 += 512) {
        int i = i0 + tid;
        int e = 0; float v = 0.f; bool in = (i < nnz), keep = false;
        if (in) { e = cand[i]; v = s[e]; keep = (v >= th); }
        unsigned m = __ballot_sync(0xffffffffu, keep);
        if (m) {
            int ldr = __ffs(m) - 1;
            int base;
            if (lane == ldr) base = atomicAdd(frc, __popc(m));
            base = __shfl_sync(0xffffffffu, base, ldr);
            if (keep) {
                int off = base + __popc(m & ((1u << lane) - 1u));
                g_fr_id[off]  = ((unsigned)bl << 16) | (unsigned)e;
                g_fr_val[off] = v;
            }
        }
        if (in) s[e] = 0.f;
    }
    __syncthreads();
    if (tid == 0) gZ.cnnz[bl] = 0;   // ready for next hop's tracking
}

// ---------------- sparse propagate (warp per frontier entry) ----------------
__global__ void prop_kernel(int t, int tin, int tout, int sn,
                            const int* __restrict__ frc, int track) {
    int gid = blockIdx.x * blockDim.x + threadIdx.x;
    int warp = gid >> 5;
    int lane = threadIdx.x & 31;
    int nwarps = (gridDim.x * blockDim.x) >> 5;
    int cnt = *frc;
    int sc = gZ.spill;
    for (int ent = warp; ent < cnt; ent += nwarps) {
        unsigned id = g_fr_id[ent];
        int bl = id >> 16;
        int e  = id & 0xFFFFu;
        float v = g_fr_val[ent] / fmaxf(gZ.nrm[tin][bl], 1e-7f);
        const float* wr = g_w + (t * BL_ + bl) * NREL_;
        float* outp = g_s[sn] + (size_t)bl * E_;
        float lsum = 0.f;
        if (lane == 0) addmsg(outp, e, wr[NREL_ - 1] * v, bl, track, lsum);
        int ch = min(gZ.cnt_h[e], CAP_);
        const unsigned* row = g_ell_h + (size_t)e * CAP_;
        for (int i = lane; i < ch; i += 32) {
            unsigned pk = row[i];
            addmsg(outp, pk & 0xFFFFu, v * wr[pk >> 16], bl, track, lsum);
        }
        int ct = min(gZ.cnt_t[e], CAP_);
        row = g_ell_t + (size_t)e * CAP_;
        for (int i = lane; i < ct; i += 32) {
            unsigned pk = row[i];
            addmsg(outp, pk & 0xFFFFu, v * wr[(pk >> 16) + R_], bl, track, lsum);
        }
        if (sc) {
            for (int i = lane; i < sc; i += 32) {
                if (g_sp_ent[i] == e) {
                    unsigned pk = g_sp_pay[i];
                    int widx = ((pk >> 16) & 0x7FFF) + ((pk >> 31) ? R_ : 0);
                    addmsg(outp, pk & 0xFFFFu, v * wr[widx], bl, track, lsum);
                }
            }
        }
        for (int o = 16; o > 0; o >>= 1) lsum += __shfl_down_sync(0xffffffffu, lsum, o);
        if (lane == 0) atomicAdd(&gZ.nrm[tout][bl], lsum);
    }
}

// ---------------- output (+ dense restore of s[1] zero-invariant) ----------------
__global__ void out_kernel(float* __restrict__ out) {
    int idx = blockIdx.x * 512 + threadIdx.x;
    if (idx >= B_ * E_) return;
    int b = idx / E_;
    int e = idx - b * E_;
    float acc = 0.f;
#pragma unroll
    for (int l = 0; l < L_; ++l) {
        int bl = b * 3 + l;
        size_t o = (size_t)bl * E_ + e;
        acc += g_s[1][o] / fmaxf(gZ.nrm[2][bl], 1e-7f);
        g_s[1][o] = 0.f;
    }
    out[idx] = acc;
}

// ---------------- launch ----------------
extern "C" void kernel_launch(void* const* d_in, const int* in_sizes, int n_in,
                              void* d_out, int out_size) {
    (void)in_sizes; (void)n_in; (void)out_size;
    const int*   input_x = (const int*)d_in[0];
    const int*   input_r = (const int*)d_in[1];
    const int*   e2      = (const int*)d_in[2];
    const int*   t2e     = (const int*)d_in[3];
    const int*   r2      = (const int*)d_in[4];
    const float* emb     = (const float*)d_in[5];

    static cudaStream_t s2 = nullptr;
    static cudaEvent_t evF = nullptr, evJ = nullptr;
    if (s2 == nullptr) {
        cudaStreamCreateWithFlags(&s2, cudaStreamNonBlocking);
        cudaEventCreateWithFlags(&evF, cudaEventDisableTiming);
        cudaEventCreateWithFlags(&evJ, cudaEventDisableTiming);
    }

    void* pZ;
    cudaGetSymbolAddress(&pZ, gZ);
    int* frA = (int*)((char*)pZ + offsetof(Zs, frA));
    int* frB = (int*)((char*)pZ + offsetof(Zs, frB));

    // main: counters zero + ELL build (enqueued first so build blocks place first)
    cudaMemsetAsync(pZ, 0, sizeof(Zs), 0);
    cudaEventRecord(evF, 0);
    build_kernel<<<(N_ / 4 + 511) / 512, 512>>>(
        (const int4*)e2, (const int4*)(t2e + N_), (const int4*)r2, (const int4*)(e2 + 2 * N_));

    // side: fused BiLSTM + logits + softmax (independent of build)
    cudaStreamWaitEvent(s2, evF, 0);
    lstm_kernel<<<96, 512, 0, s2>>>(input_r, emb,
        (const float*)d_in[6], (const float*)d_in[7], (const float*)d_in[8],
        (const float*)d_in[9], (const float*)d_in[10], (const float*)d_in[11],
        (const float*)d_in[12], (const float*)d_in[13], (const float*)d_in[14],
        (const float*)d_in[15]);
    cudaEventRecord(evJ, s2);
    cudaStreamWaitEvent(0, evJ, 0);

    hop0_kernel<<<BL_, 512>>>(input_x);
    tc_kernel<<<BL_, 512>>>(1, frA);
    prop_kernel<<<296, 256>>>(1, 0, 1, 0, frA, 1);
    tc_kernel<<<BL_, 512>>>(0, frB);
    prop_kernel<<<296, 256>>>(2, 1, 2, 1, frB, 0);
    out_kernel<<<(B_ * E_ + 511) / 512, 512>>>((float*)d_out);
}